// round 16
// baseline (speedup 1.0000x reference)
#include <cuda_runtime.h>
#include <cstdint>

// Problem constants
#define BATCH   1024
#define IN_H    128
#define IN_W    128
#define WPAD    132
#define NKW     25
#define NK      625
#define KHW     100

// Tiling (exact R9 champion config)
#define IGROUPS 5           // blockIdx.y: groups of 5 output rows
#define KL      125         // outputs per block (5 rows * 25 cols)
#define XROWS   30          // padded input rows per 5 output rows
#define XS      156         // x smem row stride (words)
#define IMGW    (XROWS*XS)  // 4680 words per image tile
#define HB      3           // images per buffer (3 independent FMA/LDS chains)
#define BUFW    (HB*IMGW)   // 14040 words
#define DEPTH   2           // double buffer
#define BSPLIT  58          // batch stripes: 58*5 = 290 blocks = 2 per SM
#define NT      128
#define SMEM_BYTES (DEPTH*BUFW*4)   // 112,320 B/block (x2 = 224.6 KB/SM)

__device__ __forceinline__ void cp16(unsigned int dst_smem, const float* src, int src_sz)
{
    asm volatile("cp.async.cg.shared.global [%0], [%1], 16, %2;\n"
                 :: "r"(dst_smem), "l"(src), "r"(src_sz));
}

// ---------------------------------------------------------------------------
// 128 threads, 2 blocks/SM. Thread kl (<125) holds its output's 100 weights
// in registers — loaded DIRECTLY from dense W (warp-coalesced: 32 consecutive
// k per sparse row; 29 same-ig blocks dedupe in L2). Computes 3 images per
// group (3 independent accumulator chains). Double-buffered cp.async fill.
// No extract kernel, no device scratch.
//
// W[((ki*5+dy)*132 + kj*5+dx) * 625 + k] == kernel_weights[k, dy, dx]
// ---------------------------------------------------------------------------
__global__ __launch_bounds__(NT, 2)
void lc2d_kernel(const float* __restrict__ x,
                 const float* __restrict__ W,
                 const float* __restrict__ bias,
                 float* __restrict__ out)
{
    extern __shared__ float xs[];
    const unsigned int xs_base = (unsigned int)__cvta_generic_to_shared(xs);

    const int bx  = blockIdx.x;   // 0..57
    const int ig  = blockIdx.y;   // 0..4
    const int tid = threadIdx.x;  // 0..127

    // zero halo columns once (padded cols -2,-1,130,131 of every staged row)
    for (int idx = tid; idx < DEPTH * HB * XROWS; idx += NT) {
        float* p = &xs[idx * XS];
        p[2] = 0.f; p[3] = 0.f; p[132] = 0.f; p[133] = 0.f;
    }

    const int kl  = tid < KL ? tid : KL - 1;
    const bool tv = tid < KL;
    const int il  = kl / 25;
    const int jj  = kl - il * 25;

    const int r0       = ig * 25 - 2;
    const int nb_total = (BATCH - 1 - bx) / BSPLIT + 1;   // 17 or 18
    const int NG       = (nb_total + HB - 1) / HB;        // 6

    const int xoff = (il * 5) * XS + jj * 5 + 2;

    // fill buffer (hg & 1) with group hg (3 images): 2880 float4
    auto fill = [&](int hg) {
        int buf = hg & 1;
        #pragma unroll
        for (int i = 0; i < 23; ++i) {
            int idx = tid + i * NT;
            if (idx < HB * XROWS * 32) {
                int bl  = idx / (XROWS * 32);
                int rem = idx - bl * (XROWS * 32);
                int rr  = rem >> 5;
                int c4  = rem & 31;
                int t   = hg * HB + bl;
                int r   = r0 + rr;
                bool v  = (t < nb_total) & (r >= 0) & (r < IN_H);
                const float* src = v
                    ? x + (size_t)(bx + t * BSPLIT) * (IN_H * IN_W) + r * IN_W + c4 * 4
                    : x;
                unsigned int dst = xs_base +
                    (unsigned int)(buf * BUFW + bl * IMGW + rr * XS + 4 + c4 * 4) * 4u;
                cp16(dst, src, v ? 16 : 0);
            }
        }
        asm volatile("cp.async.commit_group;\n");
    };

    // start the first fills BEFORE the weight prologue so DRAM for x
    // overlaps the scattered weight loads
    fill(0);
    fill(1);

    // ---- 100 weights into registers, straight from dense W ----
    // global output index k = ig*125 + kl; global row ki = k/25, col kj = k%25
    float wreg[KHW];
    {
        const int k  = ig * KL + kl;
        const int ki = k / NKW;
        const int kj = k - ki * NKW;
        const float* wp = W + (size_t)((ki * 5) * WPAD + kj * 5) * NK + k;
        #pragma unroll
        for (int dy = 0; dy < 10; ++dy) {
            #pragma unroll
            for (int dx = 0; dx < 10; ++dx)
                wreg[dy * 10 + dx] = __ldg(wp + (size_t)(dy * WPAD + dx) * NK);
        }
    }
    const float bv = __ldg(&bias[ig * KL + kl]);

    for (int g = 0; g < NG; ++g) {
        if (g + 1 < NG) asm volatile("cp.async.wait_group 1;\n");
        else            asm volatile("cp.async.wait_group 0;\n");
        __syncthreads();

        const int buf = g & 1;
        {
            const float* xpA = xs + buf * BUFW + xoff;
            const float* xpB = xpA + IMGW;
            const float* xpC = xpB + IMGW;
            float a0 = 0.f, a1 = 0.f, a2 = 0.f;
            #pragma unroll
            for (int dy = 0; dy < 10; ++dy) {
                #pragma unroll
                for (int dx = 0; dx < 10; ++dx) {
                    float w = wreg[dy * 10 + dx];
                    int   o = dy * XS + dx;
                    a0 = fmaf(xpA[o], w, a0);
                    a1 = fmaf(xpB[o], w, a1);
                    a2 = fmaf(xpC[o], w, a2);
                }
            }
            int tA = g * HB;
            int ob = ig * KL + kl;
            if (tv) {
                if (tA < nb_total)
                    out[(size_t)(bx + tA * BSPLIT) * NK + ob] = a0 + bv;
                if (tA + 1 < nb_total)
                    out[(size_t)(bx + (tA + 1) * BSPLIT) * NK + ob] = a1 + bv;
                if (tA + 2 < nb_total)
                    out[(size_t)(bx + (tA + 2) * BSPLIT) * NK + ob] = a2 + bv;
            }
        }
        __syncthreads();

        if (g + 2 < NG) fill(g + 2);
    }
}

// ---------------------------------------------------------------------------
extern "C" void kernel_launch(void* const* d_in, const int* in_sizes, int n_in,
                              void* d_out, int out_size)
{
    const float* x    = (const float*)d_in[0];   // [1024,128,128]
    const float* W    = (const float*)d_in[1];   // [17424,625]
    const float* bias = (const float*)d_in[2];   // [25,25]
    float* out = (float*)d_out;                  // [1024,25,25]

    cudaFuncSetAttribute(lc2d_kernel,
                         cudaFuncAttributeMaxDynamicSharedMemorySize, SMEM_BYTES);

    dim3 grid(BSPLIT, IGROUPS);
    lc2d_kernel<<<grid, NT, SMEM_BYTES>>>(x, W, bias, out);
}

// round 17
// speedup vs baseline: 1.6422x; 1.6422x over previous
#include <cuda_runtime.h>
#include <cstdint>

// Problem constants
#define BATCH   1024
#define IN_H    128
#define IN_W    128
#define WPAD    132
#define NKW     25
#define NK      625
#define KHW     100

// Tiling (exact R9 champion config)
#define IGROUPS 5           // blockIdx.y: groups of 5 output rows
#define KL      125         // outputs per block (5 rows * 25 cols)
#define XROWS   30          // padded input rows per 5 output rows
#define XS      156         // x smem row stride (words)
#define IMGW    (XROWS*XS)  // 4680 words per image tile
#define HB      3           // images per buffer (3 independent FMA/LDS chains)
#define BUFW    (HB*IMGW)   // 14040 words
#define DEPTH   2           // double buffer
#define BSPLIT  58          // batch stripes: 58*5 = 290 blocks = 2 per SM
#define NT      128
#define SMEM_BYTES (DEPTH*BUFW*4)   // 112,320 B/block (x2 = 224.6 KB/SM)

// Extracted weights: g_w[k*100 + dy*10 + dx]
__device__ float g_w[NK * KHW];

// ---------------------------------------------------------------------------
// Gather the 62,500 live weights out of dense W [17424 x 625].
// Transposed mapping (k fastest within a warp): READ side fully coalesced
// (warp reads 32 consecutive k of one sparse row = 128B); write side
// scattered (stride 100 words) but STG is fire-and-forget.
// W[((ki*5+dy)*132 + kj*5+dx) * 625 + k] == kernel_weights[k, dy, dx]
// ---------------------------------------------------------------------------
__global__ void extract_kernel(const float* __restrict__ W)
{
    int idx = blockIdx.x * blockDim.x + threadIdx.x;   // d*625 + k
    if (idx >= NK * KHW) return;
    int d  = idx / NK;
    int k  = idx - d * NK;
    int dy = d / 10;
    int dx = d - dy * 10;
    int ki = k / NKW;
    int kj = k - ki * NKW;
    int r  = (ki * 5 + dy) * WPAD + (kj * 5 + dx);
    g_w[k * KHW + d] = W[(size_t)r * NK + k];
}

__device__ __forceinline__ void cp16(unsigned int dst_smem, const float* src, int src_sz)
{
    asm volatile("cp.async.cg.shared.global [%0], [%1], 16, %2;\n"
                 :: "r"(dst_smem), "l"(src), "r"(src_sz));
}

// ---------------------------------------------------------------------------
// R9 champion kernel, verbatim: 128 threads, 2 blocks/SM. Thread kl (<125)
// holds its output's 100 weights in registers (contiguous float4 loads from
// g_w), computes 3 images per group (3 independent accumulator chains).
// Double-buffered cp.async fill.
// ---------------------------------------------------------------------------
__global__ __launch_bounds__(NT, 2)
void lc2d_kernel(const float* __restrict__ x,
                 const float* __restrict__ bias,
                 float* __restrict__ out)
{
    extern __shared__ float xs[];
    const unsigned int xs_base = (unsigned int)__cvta_generic_to_shared(xs);

    const int bx  = blockIdx.x;   // 0..57
    const int ig  = blockIdx.y;   // 0..4
    const int tid = threadIdx.x;  // 0..127

    // zero halo columns once (padded cols -2,-1,130,131 of every staged row)
    for (int idx = tid; idx < DEPTH * HB * XROWS; idx += NT) {
        float* p = &xs[idx * XS];
        p[2] = 0.f; p[3] = 0.f; p[132] = 0.f; p[133] = 0.f;
    }

    const int kl  = tid < KL ? tid : KL - 1;
    const bool tv = tid < KL;
    const int il  = kl / 25;
    const int jj  = kl - il * 25;

    // ---- 100 weights into registers ----
    float4 w4[25];
    {
        const float4* wg = reinterpret_cast<const float4*>(g_w) + (ig * KL + kl) * 25;
        #pragma unroll
        for (int j = 0; j < 25; ++j) w4[j] = __ldg(&wg[j]);
    }
    const float bv = __ldg(&bias[ig * KL + kl]);

    const int r0       = ig * 25 - 2;
    const int nb_total = (BATCH - 1 - bx) / BSPLIT + 1;   // 17 or 18
    const int NG       = (nb_total + HB - 1) / HB;        // 6

    const int xoff = (il * 5) * XS + jj * 5 + 2;

    // fill buffer (hg & 1) with group hg (3 images): 2880 float4
    auto fill = [&](int hg) {
        int buf = hg & 1;
        #pragma unroll
        for (int i = 0; i < 23; ++i) {
            int idx = tid + i * NT;
            if (idx < HB * XROWS * 32) {
                int bl  = idx / (XROWS * 32);
                int rem = idx - bl * (XROWS * 32);
                int rr  = rem >> 5;
                int c4  = rem & 31;
                int t   = hg * HB + bl;
                int r   = r0 + rr;
                bool v  = (t < nb_total) & (r >= 0) & (r < IN_H);
                const float* src = v
                    ? x + (size_t)(bx + t * BSPLIT) * (IN_H * IN_W) + r * IN_W + c4 * 4
                    : x;
                unsigned int dst = xs_base +
                    (unsigned int)(buf * BUFW + bl * IMGW + rr * XS + 4 + c4 * 4) * 4u;
                cp16(dst, src, v ? 16 : 0);
            }
        }
        asm volatile("cp.async.commit_group;\n");
    };

    fill(0);
    fill(1);

    for (int g = 0; g < NG; ++g) {
        if (g + 1 < NG) asm volatile("cp.async.wait_group 1;\n");
        else            asm volatile("cp.async.wait_group 0;\n");
        __syncthreads();

        const int buf = g & 1;
        {
            const float* xpA = xs + buf * BUFW + xoff;
            const float* xpB = xpA + IMGW;
            const float* xpC = xpB + IMGW;
            float a0 = 0.f, a1 = 0.f, a2 = 0.f;
            const float* wf = reinterpret_cast<const float*>(w4);
            #pragma unroll
            for (int dy = 0; dy < 10; ++dy) {
                #pragma unroll
                for (int dx = 0; dx < 10; ++dx) {
                    float w = wf[dy * 10 + dx];
                    int   o = dy * XS + dx;
                    a0 = fmaf(xpA[o], w, a0);
                    a1 = fmaf(xpB[o], w, a1);
                    a2 = fmaf(xpC[o], w, a2);
                }
            }
            int tA = g * HB;
            int ob = ig * KL + kl;
            if (tv) {
                if (tA < nb_total)
                    out[(size_t)(bx + tA * BSPLIT) * NK + ob] = a0 + bv;
                if (tA + 1 < nb_total)
                    out[(size_t)(bx + (tA + 1) * BSPLIT) * NK + ob] = a1 + bv;
                if (tA + 2 < nb_total)
                    out[(size_t)(bx + (tA + 2) * BSPLIT) * NK + ob] = a2 + bv;
            }
        }
        __syncthreads();

        if (g + 2 < NG) fill(g + 2);
    }
}

// ---------------------------------------------------------------------------
extern "C" void kernel_launch(void* const* d_in, const int* in_sizes, int n_in,
                              void* d_out, int out_size)
{
    const float* x    = (const float*)d_in[0];   // [1024,128,128]
    const float* W    = (const float*)d_in[1];   // [17424,625]
    const float* bias = (const float*)d_in[2];   // [25,25]
    float* out = (float*)d_out;                  // [1024,25,25]

    cudaFuncSetAttribute(lc2d_kernel,
                         cudaFuncAttributeMaxDynamicSharedMemorySize, SMEM_BYTES);

    extract_kernel<<<(NK * KHW + 255) / 256, 256>>>(W);

    dim3 grid(BSPLIT, IGROUPS);
    lc2d_kernel<<<grid, NT, SMEM_BYTES>>>(x, bias, out);
}